// round 3
// baseline (speedup 1.0000x reference)
#include <cuda_runtime.h>

#define B_   4
#define L_   1024
#define D_   1280
#define H_   20
#define DH_  64
#define BH_  80            // B_*H_
#define M_   4096          // B_*L_
#define ALPHA 0.48f
#define QSCALE 0.125f      // 1/sqrt(64)

// Scratch (device globals: allocation-free per harness rules)
__device__ float g_Q[M_ * D_];
__device__ float g_K[M_ * D_];
__device__ float g_V[M_ * D_];
__device__ float g_C[M_ * D_];

// ---------------------------------------------------------------------------
// SGEMM: C[M,N] = A[M,K] @ B[K,N] (+ bias). 128x128 tile, BK=8, 8x8/thread.
// ---------------------------------------------------------------------------
#define BM  128
#define BN  128
#define BKK 8
#define TM  8
#define TN  8

__global__ __launch_bounds__(256) void sgemm_kernel(
    const float* __restrict__ A, const float* __restrict__ Bm,
    const float* __restrict__ bias, float* __restrict__ C,
    int M, int N, int K)
{
    __shared__ float As[BKK][BM];
    __shared__ float Bs[BKK][BN];

    const int tid  = threadIdx.x;
    const int brow = blockIdx.y * BM;
    const int bcol = blockIdx.x * BN;

    const int arow = tid >> 1;          // 0..127
    const int acol = (tid & 1) * 4;     // 0 or 4
    const int brl  = tid >> 5;          // 0..7
    const int bcl  = (tid & 31) * 4;    // 0..124
    const int tx   = tid & 15;
    const int ty   = tid >> 4;

    float acc[TM][TN] = {};
    const float* Ab = A + (size_t)(brow + arow) * K + acol;
    const float* Bb = Bm + (size_t)brl * N + bcol + bcl;

    for (int k0 = 0; k0 < K; k0 += BKK) {
        float4 a4 = *(const float4*)(Ab + k0);
        As[acol + 0][arow] = a4.x;
        As[acol + 1][arow] = a4.y;
        As[acol + 2][arow] = a4.z;
        As[acol + 3][arow] = a4.w;
        float4 b4 = *(const float4*)(Bb + (size_t)k0 * N);
        *(float4*)(&Bs[brl][bcl]) = b4;
        __syncthreads();

        #pragma unroll
        for (int kk = 0; kk < BKK; kk++) {
            float ar[TM], br[TN];
            #pragma unroll
            for (int i = 0; i < TM; i++) ar[i] = As[kk][ty * TM + i];
            #pragma unroll
            for (int j = 0; j < TN; j++) br[j] = Bs[kk][tx * TN + j];
            #pragma unroll
            for (int i = 0; i < TM; i++)
                #pragma unroll
                for (int j = 0; j < TN; j++)
                    acc[i][j] += ar[i] * br[j];
        }
        __syncthreads();
    }

    if (bias) {
        #pragma unroll
        for (int i = 0; i < TM; i++)
            #pragma unroll
            for (int j = 0; j < TN; j++)
                acc[i][j] += bias[bcol + tx * TN + j];
    }

    #pragma unroll
    for (int i = 0; i < TM; i++) {
        float* crow = C + (size_t)(brow + ty * TM + i) * N + bcol + tx * TN;
        #pragma unroll
        for (int j = 0; j < TN; j += 4) {
            float4 v;
            v.x = acc[i][j + 0];
            v.y = acc[i][j + 1];
            v.z = acc[i][j + 2];
            v.w = acc[i][j + 3];
            *(float4*)(crow + j) = v;
        }
    }
}

// ---------------------------------------------------------------------------
// Flash attention: one thread per q row (128 rows/block), KV tiles of 32.
// KV length = 2048: first 1024 from self K/V, last 1024 from alpha*K_bg/V_bg.
// ---------------------------------------------------------------------------
__global__ __launch_bounds__(128) void attn_kernel(
    const float* __restrict__ Q, const float* __restrict__ K,
    const float* __restrict__ V, const float* __restrict__ Kbg,
    const float* __restrict__ Vbg, float* __restrict__ C)
{
    __shared__ float Ks[32 * 64];
    __shared__ float Vs[32 * 64];
    __shared__ float Ss[32 * 128];

    const int bh   = blockIdx.y;
    const int b    = bh / H_;
    const int h    = bh % H_;
    const int tid  = threadIdx.x;
    const int qrow = blockIdx.x * 128 + tid;

    const float* qptr = Q + (size_t)(b * L_ + qrow) * D_ + h * DH_;
    float q[DH_];
    #pragma unroll
    for (int d = 0; d < DH_; d++) q[d] = qptr[d] * QSCALE;

    float o[DH_];
    #pragma unroll
    for (int d = 0; d < DH_; d++) o[d] = 0.f;
    float m = -1e30f, l = 0.f;

    for (int t = 0; t < 64; t++) {
        const int jbase = t * 32;
        __syncthreads();   // protect Ks/Vs reads of previous tile
        if (jbase < L_) {
            #pragma unroll
            for (int i = 0; i < 4; i++) {
                int idx = tid + i * 128;        // float4 index 0..511
                int jj  = idx >> 4;
                int dd  = (idx & 15) * 4;
                *(float4*)(Ks + jj * 64 + dd) =
                    *(const float4*)(K + (size_t)(b * L_ + jbase + jj) * D_ + h * DH_ + dd);
                *(float4*)(Vs + jj * 64 + dd) =
                    *(const float4*)(V + (size_t)(b * L_ + jbase + jj) * D_ + h * DH_ + dd);
            }
        } else {
            const int jb = jbase - L_;
            #pragma unroll
            for (int i = 0; i < 4; i++) {
                int idx = tid + i * 128;
                int jj  = idx >> 4;
                int dd  = (idx & 15) * 4;
                float4 k4 = *(const float4*)(Kbg + ((size_t)bh * L_ + jb + jj) * DH_ + dd);
                k4.x *= ALPHA; k4.y *= ALPHA; k4.z *= ALPHA; k4.w *= ALPHA;
                *(float4*)(Ks + jj * 64 + dd) = k4;
                float4 v4 = *(const float4*)(Vbg + ((size_t)bh * L_ + jb + jj) * DH_ + dd);
                v4.x *= ALPHA; v4.y *= ALPHA; v4.z *= ALPHA; v4.w *= ALPHA;
                *(float4*)(Vs + jj * 64 + dd) = v4;
            }
        }
        __syncthreads();

        // scores for this tile (broadcast smem reads; 4 accumulators for ILP)
        float tmax = -1e30f;
        for (int j = 0; j < 32; j++) {
            float a0 = 0.f, a1 = 0.f, a2 = 0.f, a3 = 0.f;
            #pragma unroll
            for (int d = 0; d < DH_; d += 4) {
                a0 += q[d + 0] * Ks[j * 64 + d + 0];
                a1 += q[d + 1] * Ks[j * 64 + d + 1];
                a2 += q[d + 2] * Ks[j * 64 + d + 2];
                a3 += q[d + 3] * Ks[j * 64 + d + 3];
            }
            float s = (a0 + a1) + (a2 + a3);
            Ss[j * 128 + tid] = s;     // thread-private slot, conflict-free
            tmax = fmaxf(tmax, s);
        }

        const float mnew = fmaxf(m, tmax);
        const float corr = __expf(m - mnew);   // first tile: exp(-inf-ish) = 0
        l *= corr;
        #pragma unroll
        for (int d = 0; d < DH_; d++) o[d] *= corr;

        for (int j = 0; j < 32; j++) {
            float p = __expf(Ss[j * 128 + tid] - mnew);
            l += p;
            #pragma unroll
            for (int d = 0; d < DH_; d++) o[d] += p * Vs[j * 64 + d];
        }
        m = mnew;
    }

    const float inv = 1.f / l;
    float* cp = C + (size_t)(b * L_ + qrow) * D_ + h * DH_;
    #pragma unroll
    for (int d = 0; d < DH_; d++) cp[d] = o[d] * inv;
}

// ---------------------------------------------------------------------------
extern "C" void kernel_launch(void* const* d_in, const int* in_sizes, int n_in,
                              void* d_out, int out_size)
{
    const float* hs  = (const float*)d_in[0];
    const float* Wq  = (const float*)d_in[1];
    const float* Wk  = (const float*)d_in[2];
    const float* Wv  = (const float*)d_in[3];
    const float* Wo  = (const float*)d_in[4];
    const float* bo  = (const float*)d_in[5];
    const float* Kbg = (const float*)d_in[6];
    const float* Vbg = (const float*)d_in[7];
    float* out = (float*)d_out;

    float *q, *k, *v, *c;
    cudaGetSymbolAddress((void**)&q, g_Q);
    cudaGetSymbolAddress((void**)&k, g_K);
    cudaGetSymbolAddress((void**)&v, g_V);
    cudaGetSymbolAddress((void**)&c, g_C);

    dim3 gg(D_ / BN, M_ / BM);   // (10, 32)
    sgemm_kernel<<<gg, 256>>>(hs, Wq, nullptr, q, M_, D_, D_);
    sgemm_kernel<<<gg, 256>>>(hs, Wk, nullptr, k, M_, D_, D_);
    sgemm_kernel<<<gg, 256>>>(hs, Wv, nullptr, v, M_, D_, D_);

    attn_kernel<<<dim3(L_ / 128, BH_), 128>>>(q, k, v, Kbg, Vbg, c);

    sgemm_kernel<<<gg, 256>>>(c, Wo, bo, out, M_, D_, D_);
}

// round 7
// speedup vs baseline: 1.3807x; 1.3807x over previous
#include <cuda_runtime.h>
#include <cstdint>

#define B_   4
#define L_   1024
#define D_   1280
#define H_   20
#define DH_  64
#define BH_  80            // B_*H_
#define M_   4096          // B_*L_
#define K_   1280
#define N_   1280
#define ALPHA 0.48f
#define QSCALE 0.125f      // 1/sqrt(64)

// Scratch (device globals: allocation-free per harness rules)
__device__ float g_Q[M_ * D_];
__device__ float g_K[M_ * D_];
__device__ float g_V[M_ * D_];
__device__ float g_C[M_ * D_];

// ---------------------------------------------------------------------------
// TF32 tensor-core GEMM: C[M,1280] = A[M,1280] @ B[1280,1280] (+bias)
// 128x128 block tile, BK=16, 8 warps (4x2), warp tile 32x64, mma.m16n8k8.tf32
// ---------------------------------------------------------------------------
__device__ __forceinline__ uint32_t f2tf(float f) {
    uint32_t u;
    asm("cvt.rna.tf32.f32 %0, %1;" : "=r"(u) : "f"(f));
    return u;
}

__device__ __forceinline__ void mma_tf32(float* c, const uint32_t* a, const uint32_t* b) {
    asm volatile(
        "mma.sync.aligned.m16n8k8.row.col.f32.tf32.tf32.f32 "
        "{%0,%1,%2,%3}, {%4,%5,%6,%7}, {%8,%9}, {%0,%1,%2,%3};\n"
        : "+f"(c[0]), "+f"(c[1]), "+f"(c[2]), "+f"(c[3])
        : "r"(a[0]), "r"(a[1]), "r"(a[2]), "r"(a[3]), "r"(b[0]), "r"(b[1]));
}

#define AS_STRIDE 20    // conflict-free frag loads: banks (20m+k)%32 permute
#define BS_STRIDE 136   // conflict-free frag loads: banks (8q+g)%32 permute

__global__ __launch_bounds__(256) void tf32_gemm_kernel(
    const float* __restrict__ A, const float* __restrict__ Bm,
    const float* __restrict__ bias, float* __restrict__ C)
{
    __shared__ uint32_t As[128 * AS_STRIDE];   // [m=128][k=16] row-major, stride 20
    __shared__ uint32_t Bs[16 * BS_STRIDE];    // [k=16][n=128] row-major, stride 136

    const int tid  = threadIdx.x;
    const int brow = blockIdx.y * 128;
    const int bcol = blockIdx.x * 128;

    const int lane   = tid & 31;
    const int warp   = tid >> 5;
    const int warp_m = (warp >> 1) * 32;   // 0,32,64,96
    const int warp_n = (warp & 1) * 64;    // 0,64
    const int g      = lane >> 2;          // 0..7
    const int q      = lane & 3;           // 0..3

    // loader mapping
    const int arow = tid >> 1;             // 0..127
    const int ac8  = (tid & 1) * 8;        // 0 or 8
    const int bkr  = tid >> 4;             // 0..15
    const int bc8  = (tid & 15) * 8;       // 0..120

    const float* Ap = A + (size_t)(brow + arow) * K_ + ac8;
    const float* Bp = Bm + (size_t)bkr * N_ + bcol + bc8;

    float acc[2][8][4];
    #pragma unroll
    for (int i = 0; i < 2; i++)
        #pragma unroll
        for (int j = 0; j < 8; j++)
            #pragma unroll
            for (int r = 0; r < 4; r++) acc[i][j][r] = 0.f;

    for (int k0 = 0; k0 < K_; k0 += 16) {
        // ---- global -> smem (convert to tf32 on the way) ----
        float4 a4a = *(const float4*)(Ap + k0);
        float4 a4b = *(const float4*)(Ap + k0 + 4);
        float4 b4a = *(const float4*)(Bp + (size_t)k0 * N_);
        float4 b4b = *(const float4*)(Bp + (size_t)k0 * N_ + 4);

        uint32_t* asd = &As[arow * AS_STRIDE + ac8];
        asd[0] = f2tf(a4a.x); asd[1] = f2tf(a4a.y);
        asd[2] = f2tf(a4a.z); asd[3] = f2tf(a4a.w);
        asd[4] = f2tf(a4b.x); asd[5] = f2tf(a4b.y);
        asd[6] = f2tf(a4b.z); asd[7] = f2tf(a4b.w);

        uint32_t* bsd = &Bs[bkr * BS_STRIDE + bc8];
        bsd[0] = f2tf(b4a.x); bsd[1] = f2tf(b4a.y);
        bsd[2] = f2tf(b4a.z); bsd[3] = f2tf(b4a.w);
        bsd[4] = f2tf(b4b.x); bsd[5] = f2tf(b4b.y);
        bsd[6] = f2tf(b4b.z); bsd[7] = f2tf(b4b.w);

        __syncthreads();

        // ---- two k-steps of 8 ----
        #pragma unroll
        for (int ks = 0; ks < 16; ks += 8) {
            uint32_t af[2][4];
            #pragma unroll
            for (int i = 0; i < 2; i++) {
                const int m0 = warp_m + i * 16 + g;
                af[i][0] = As[m0 * AS_STRIDE + ks + q];
                af[i][1] = As[(m0 + 8) * AS_STRIDE + ks + q];
                af[i][2] = As[m0 * AS_STRIDE + ks + q + 4];
                af[i][3] = As[(m0 + 8) * AS_STRIDE + ks + q + 4];
            }
            #pragma unroll
            for (int j = 0; j < 8; j++) {
                uint32_t bf[2];
                const int n0 = warp_n + j * 8 + g;
                bf[0] = Bs[(ks + q) * BS_STRIDE + n0];
                bf[1] = Bs[(ks + q + 4) * BS_STRIDE + n0];
                mma_tf32(acc[0][j], af[0], bf);
                mma_tf32(acc[1][j], af[1], bf);
            }
        }
        __syncthreads();
    }

    // ---- epilogue ----
    #pragma unroll
    for (int i = 0; i < 2; i++) {
        const int row0 = brow + warp_m + i * 16 + g;
        #pragma unroll
        for (int j = 0; j < 8; j++) {
            const int col = bcol + warp_n + j * 8 + 2 * q;
            float b0 = 0.f, b1 = 0.f;
            if (bias) { b0 = bias[col]; b1 = bias[col + 1]; }
            float2 v0 = make_float2(acc[i][j][0] + b0, acc[i][j][1] + b1);
            float2 v1 = make_float2(acc[i][j][2] + b0, acc[i][j][3] + b1);
            *(float2*)(C + (size_t)row0 * N_ + col) = v0;
            *(float2*)(C + (size_t)(row0 + 8) * N_ + col) = v1;
        }
    }
}

// ---------------------------------------------------------------------------
// Flash attention: one thread per q row (128 rows/block), KV tiles of 32.
// KV length = 2048: first 1024 from self K/V, last 1024 from alpha*K_bg/V_bg.
// ---------------------------------------------------------------------------
__global__ __launch_bounds__(128) void attn_kernel(
    const float* __restrict__ Q, const float* __restrict__ K,
    const float* __restrict__ V, const float* __restrict__ Kbg,
    const float* __restrict__ Vbg, float* __restrict__ C)
{
    __shared__ float Ks[32 * 64];
    __shared__ float Vs[32 * 64];
    __shared__ float Ss[32 * 128];

    const int bh   = blockIdx.y;
    const int b    = bh / H_;
    const int h    = bh % H_;
    const int tid  = threadIdx.x;
    const int qrow = blockIdx.x * 128 + tid;

    const float* qptr = Q + (size_t)(b * L_ + qrow) * D_ + h * DH_;
    float q[DH_];
    #pragma unroll
    for (int d = 0; d < DH_; d++) q[d] = qptr[d] * QSCALE;

    float o[DH_];
    #pragma unroll
    for (int d = 0; d < DH_; d++) o[d] = 0.f;
    float m = -1e30f, l = 0.f;

    for (int t = 0; t < 64; t++) {
        const int jbase = t * 32;
        __syncthreads();   // protect Ks/Vs reads of previous tile
        if (jbase < L_) {
            #pragma unroll
            for (int i = 0; i < 4; i++) {
                int idx = tid + i * 128;        // float4 index 0..511
                int jj  = idx >> 4;
                int dd  = (idx & 15) * 4;
                *(float4*)(Ks + jj * 64 + dd) =
                    *(const float4*)(K + (size_t)(b * L_ + jbase + jj) * D_ + h * DH_ + dd);
                *(float4*)(Vs + jj * 64 + dd) =
                    *(const float4*)(V + (size_t)(b * L_ + jbase + jj) * D_ + h * DH_ + dd);
            }
        } else {
            const int jb = jbase - L_;
            #pragma unroll
            for (int i = 0; i < 4; i++) {
                int idx = tid + i * 128;
                int jj  = idx >> 4;
                int dd  = (idx & 15) * 4;
                float4 k4 = *(const float4*)(Kbg + ((size_t)bh * L_ + jb + jj) * DH_ + dd);
                k4.x *= ALPHA; k4.y *= ALPHA; k4.z *= ALPHA; k4.w *= ALPHA;
                *(float4*)(Ks + jj * 64 + dd) = k4;
                float4 v4 = *(const float4*)(Vbg + ((size_t)bh * L_ + jb + jj) * DH_ + dd);
                v4.x *= ALPHA; v4.y *= ALPHA; v4.z *= ALPHA; v4.w *= ALPHA;
                *(float4*)(Vs + jj * 64 + dd) = v4;
            }
        }
        __syncthreads();

        // scores for this tile (broadcast smem reads; 4 accumulators for ILP)
        float tmax = -1e30f;
        for (int j = 0; j < 32; j++) {
            float a0 = 0.f, a1 = 0.f, a2 = 0.f, a3 = 0.f;
            #pragma unroll
            for (int d = 0; d < DH_; d += 4) {
                a0 += q[d + 0] * Ks[j * 64 + d + 0];
                a1 += q[d + 1] * Ks[j * 64 + d + 1];
                a2 += q[d + 2] * Ks[j * 64 + d + 2];
                a3 += q[d + 3] * Ks[j * 64 + d + 3];
            }
            float s = (a0 + a1) + (a2 + a3);
            Ss[j * 128 + tid] = s;     // thread-private slot, conflict-free
            tmax = fmaxf(tmax, s);
        }

        const float mnew = fmaxf(m, tmax);
        const float corr = __expf(m - mnew);   // first tile: exp(-inf-ish) = 0
        l *= corr;
        #pragma unroll
        for (int d = 0; d < DH_; d++) o[d] *= corr;

        for (int j = 0; j < 32; j++) {
            float p = __expf(Ss[j * 128 + tid] - mnew);
            l += p;
            #pragma unroll
            for (int d = 0; d < DH_; d++) o[d] += p * Vs[j * 64 + d];
        }
        m = mnew;
    }

    const float inv = 1.f / l;
    float* cp = C + (size_t)(b * L_ + qrow) * D_ + h * DH_;
    #pragma unroll
    for (int d = 0; d < DH_; d++) cp[d] = o[d] * inv;
}

// ---------------------------------------------------------------------------
extern "C" void kernel_launch(void* const* d_in, const int* in_sizes, int n_in,
                              void* d_out, int out_size)
{
    const float* hs  = (const float*)d_in[0];
    const float* Wq  = (const float*)d_in[1];
    const float* Wk  = (const float*)d_in[2];
    const float* Wv  = (const float*)d_in[3];
    const float* Wo  = (const float*)d_in[4];
    const float* bo  = (const float*)d_in[5];
    const float* Kbg = (const float*)d_in[6];
    const float* Vbg = (const float*)d_in[7];
    float* out = (float*)d_out;

    float *q, *k, *v, *c;
    cudaGetSymbolAddress((void**)&q, g_Q);
    cudaGetSymbolAddress((void**)&k, g_K);
    cudaGetSymbolAddress((void**)&v, g_V);
    cudaGetSymbolAddress((void**)&c, g_C);

    dim3 gg(N_ / 128, M_ / 128);   // (10, 32)
    tf32_gemm_kernel<<<gg, 256>>>(hs, Wq, nullptr, q);
    tf32_gemm_kernel<<<gg, 256>>>(hs, Wk, nullptr, k);
    tf32_gemm_kernel<<<gg, 256>>>(hs, Wv, nullptr, v);

    attn_kernel<<<dim3(L_ / 128, BH_), 128>>>(q, k, v, Kbg, Vbg, c);

    tf32_gemm_kernel<<<gg, 256>>>(c, Wo, bo, out);
}

// round 13
// speedup vs baseline: 2.6683x; 1.9325x over previous
#include <cuda_runtime.h>
#include <cuda_bf16.h>
#include <cstdint>

#define B_   4
#define L_   1024
#define D_   1280
#define H_   20
#define DH_  64
#define BH_  80            // B_*H_
#define M_   4096          // B_*L_
#define K_   1280
#define N_   1280
#define ALPHA 0.48f
#define QSCALE 0.125f      // 1/sqrt(64)

// Scratch (device globals: allocation-free per harness rules)
__device__ float g_Q[M_ * D_];
__device__ float g_K[M_ * D_];
__device__ float g_V[M_ * D_];
__device__ float g_C[M_ * D_];

// ---------------------------------------------------------------------------
// TF32 tensor-core GEMM: C[M,1280] = A[M,1280] @ B[1280,1280] (+bias)
// ---------------------------------------------------------------------------
__device__ __forceinline__ uint32_t f2tf(float f) {
    uint32_t u;
    asm("cvt.rna.tf32.f32 %0, %1;" : "=r"(u) : "f"(f));
    return u;
}

__device__ __forceinline__ void mma_tf32(float* c, const uint32_t* a, const uint32_t* b) {
    asm volatile(
        "mma.sync.aligned.m16n8k8.row.col.f32.tf32.tf32.f32 "
        "{%0,%1,%2,%3}, {%4,%5,%6,%7}, {%8,%9}, {%0,%1,%2,%3};\n"
        : "+f"(c[0]), "+f"(c[1]), "+f"(c[2]), "+f"(c[3])
        : "r"(a[0]), "r"(a[1]), "r"(a[2]), "r"(a[3]), "r"(b[0]), "r"(b[1]));
}

#define AS_STRIDE 20
#define BS_STRIDE 136

__global__ __launch_bounds__(256) void tf32_gemm_kernel(
    const float* __restrict__ A, const float* __restrict__ Bm,
    const float* __restrict__ bias, float* __restrict__ C)
{
    __shared__ uint32_t As[128 * AS_STRIDE];
    __shared__ uint32_t Bs[16 * BS_STRIDE];

    const int tid  = threadIdx.x;
    const int brow = blockIdx.y * 128;
    const int bcol = blockIdx.x * 128;

    const int lane   = tid & 31;
    const int warp   = tid >> 5;
    const int warp_m = (warp >> 1) * 32;
    const int warp_n = (warp & 1) * 64;
    const int g      = lane >> 2;
    const int q      = lane & 3;

    const int arow = tid >> 1;
    const int ac8  = (tid & 1) * 8;
    const int bkr  = tid >> 4;
    const int bc8  = (tid & 15) * 8;

    const float* Ap = A + (size_t)(brow + arow) * K_ + ac8;
    const float* Bp = Bm + (size_t)bkr * N_ + bcol + bc8;

    float acc[2][8][4];
    #pragma unroll
    for (int i = 0; i < 2; i++)
        #pragma unroll
        for (int j = 0; j < 8; j++)
            #pragma unroll
            for (int r = 0; r < 4; r++) acc[i][j][r] = 0.f;

    for (int k0 = 0; k0 < K_; k0 += 16) {
        float4 a4a = *(const float4*)(Ap + k0);
        float4 a4b = *(const float4*)(Ap + k0 + 4);
        float4 b4a = *(const float4*)(Bp + (size_t)k0 * N_);
        float4 b4b = *(const float4*)(Bp + (size_t)k0 * N_ + 4);

        uint32_t* asd = &As[arow * AS_STRIDE + ac8];
        asd[0] = f2tf(a4a.x); asd[1] = f2tf(a4a.y);
        asd[2] = f2tf(a4a.z); asd[3] = f2tf(a4a.w);
        asd[4] = f2tf(a4b.x); asd[5] = f2tf(a4b.y);
        asd[6] = f2tf(a4b.z); asd[7] = f2tf(a4b.w);

        uint32_t* bsd = &Bs[bkr * BS_STRIDE + bc8];
        bsd[0] = f2tf(b4a.x); bsd[1] = f2tf(b4a.y);
        bsd[2] = f2tf(b4a.z); bsd[3] = f2tf(b4a.w);
        bsd[4] = f2tf(b4b.x); bsd[5] = f2tf(b4b.y);
        bsd[6] = f2tf(b4b.z); bsd[7] = f2tf(b4b.w);

        __syncthreads();

        #pragma unroll
        for (int ks = 0; ks < 16; ks += 8) {
            uint32_t af[2][4];
            #pragma unroll
            for (int i = 0; i < 2; i++) {
                const int m0 = warp_m + i * 16 + g;
                af[i][0] = As[m0 * AS_STRIDE + ks + q];
                af[i][1] = As[(m0 + 8) * AS_STRIDE + ks + q];
                af[i][2] = As[m0 * AS_STRIDE + ks + q + 4];
                af[i][3] = As[(m0 + 8) * AS_STRIDE + ks + q + 4];
            }
            #pragma unroll
            for (int j = 0; j < 8; j++) {
                uint32_t bf[2];
                const int n0 = warp_n + j * 8 + g;
                bf[0] = Bs[(ks + q) * BS_STRIDE + n0];
                bf[1] = Bs[(ks + q + 4) * BS_STRIDE + n0];
                mma_tf32(acc[0][j], af[0], bf);
                mma_tf32(acc[1][j], af[1], bf);
            }
        }
        __syncthreads();
    }

    #pragma unroll
    for (int i = 0; i < 2; i++) {
        const int row0 = brow + warp_m + i * 16 + g;
        #pragma unroll
        for (int j = 0; j < 8; j++) {
            const int col = bcol + warp_n + j * 8 + 2 * q;
            float b0 = 0.f, b1 = 0.f;
            if (bias) { b0 = bias[col]; b1 = bias[col + 1]; }
            float2 v0 = make_float2(acc[i][j][0] + b0, acc[i][j][1] + b1);
            float2 v1 = make_float2(acc[i][j][2] + b0, acc[i][j][3] + b1);
            *(float2*)(C + (size_t)row0 * N_ + col) = v0;
            *(float2*)(C + (size_t)(row0 + 8) * N_ + col) = v1;
        }
    }
}

// ---------------------------------------------------------------------------
// bf16-split tensor-core flash attention.
// Block: 64 q-rows, 4 warps x 16 rows. KV tiles of 64 (32 iters over 2048).
// KV kept fp32 in smem (K stride 72, V stride 68: conflict-free frag LDS);
// hi/lo bf16 split done in registers. 3-term mma: hh + hl + lh (err ~2^-16).
// ---------------------------------------------------------------------------
#define KSTR 72
#define VSTR 68

__device__ __forceinline__ void mma_bf16(float* c, const uint32_t* a, const uint32_t* b) {
    asm volatile(
        "mma.sync.aligned.m16n8k16.row.col.f32.bf16.bf16.f32 "
        "{%0,%1,%2,%3}, {%4,%5,%6,%7}, {%8,%9}, {%0,%1,%2,%3};\n"
        : "+f"(c[0]), "+f"(c[1]), "+f"(c[2]), "+f"(c[3])
        : "r"(a[0]), "r"(a[1]), "r"(a[2]), "r"(a[3]), "r"(b[0]), "r"(b[1]));
}

// pack (x,y) into bf16x2 hi part + bf16x2 residual part (element0 in low half)
__device__ __forceinline__ void split2(float x, float y, uint32_t& hi, uint32_t& lo) {
    __nv_bfloat162 h2 = __floats2bfloat162_rn(x, y);
    float rx = x - __bfloat162float(h2.x);
    float ry = y - __bfloat162float(h2.y);
    __nv_bfloat162 l2 = __floats2bfloat162_rn(rx, ry);
    hi = *reinterpret_cast<uint32_t*>(&h2);
    lo = *reinterpret_cast<uint32_t*>(&l2);
}

__global__ __launch_bounds__(128) void attn_mma_kernel(
    const float* __restrict__ Q, const float* __restrict__ K,
    const float* __restrict__ V, const float* __restrict__ Kbg,
    const float* __restrict__ Vbg, float* __restrict__ C)
{
    __shared__ float Ks[64 * KSTR];
    __shared__ float Vs[64 * VSTR];

    const int bh    = blockIdx.y;
    const int b     = bh / H_;
    const int h     = bh % H_;
    const int qbase = blockIdx.x * 64;
    const int tid   = threadIdx.x;
    const int lane  = tid & 31;
    const int warp  = tid >> 5;
    const int g     = lane >> 2;     // 0..7
    const int qq    = lane & 3;      // 0..3

    const int r  = qbase + warp * 16 + g;   // this lane's q rows: r, r+8

    // ---- load + pre-split Q fragments (held for whole kernel) ----
    uint32_t qh[4][4], ql[4][4];
    {
        const float* q0 = Q + (size_t)(b * L_ + r) * D_ + h * DH_;
        const float* q1 = Q + (size_t)(b * L_ + r + 8) * D_ + h * DH_;
        #pragma unroll
        for (int kf = 0; kf < 4; kf++) {
            const int d0 = kf * 16 + 2 * qq;
            split2(q0[d0] * QSCALE,     q0[d0 + 1] * QSCALE, qh[kf][0], ql[kf][0]);
            split2(q1[d0] * QSCALE,     q1[d0 + 1] * QSCALE, qh[kf][1], ql[kf][1]);
            split2(q0[d0 + 8] * QSCALE, q0[d0 + 9] * QSCALE, qh[kf][2], ql[kf][2]);
            split2(q1[d0 + 8] * QSCALE, q1[d0 + 9] * QSCALE, qh[kf][3], ql[kf][3]);
        }
    }

    float O[8][4];
    #pragma unroll
    for (int j = 0; j < 8; j++)
        #pragma unroll
        for (int i = 0; i < 4; i++) O[j][i] = 0.f;
    float m0 = -1e30f, m1 = -1e30f;   // running max for rows r, r+8
    float l0 = 0.f,    l1 = 0.f;      // lane-partial softmax sums

    for (int t = 0; t < 32; t++) {
        __syncthreads();
        // ---- load KV tile t into smem (fp32), alpha folded for bg half ----
        #pragma unroll
        for (int i = 0; i < 8; i++) {
            const int idx = tid + i * 128;          // 1024 float4 slots
            const int row = idx >> 4;
            const int c4  = (idx & 15) << 2;
            float4 k4, v4;
            if (t < 16) {
                k4 = *(const float4*)(K + (size_t)(b * L_ + t * 64 + row) * D_ + h * DH_ + c4);
                v4 = *(const float4*)(V + (size_t)(b * L_ + t * 64 + row) * D_ + h * DH_ + c4);
            } else {
                k4 = *(const float4*)(Kbg + ((size_t)bh * L_ + (t - 16) * 64 + row) * DH_ + c4);
                v4 = *(const float4*)(Vbg + ((size_t)bh * L_ + (t - 16) * 64 + row) * DH_ + c4);
                k4.x *= ALPHA; k4.y *= ALPHA; k4.z *= ALPHA; k4.w *= ALPHA;
                v4.x *= ALPHA; v4.y *= ALPHA; v4.z *= ALPHA; v4.w *= ALPHA;
            }
            *(float4*)(Ks + row * KSTR + c4) = k4;
            *(float4*)(Vs + row * VSTR + c4) = v4;
        }
        __syncthreads();

        // ---- scores S[16q x 64kv] via 3-term bf16 mma ----
        float S[8][4];
        #pragma unroll
        for (int j = 0; j < 8; j++)
            #pragma unroll
            for (int i = 0; i < 4; i++) S[j][i] = 0.f;

        #pragma unroll
        for (int ks = 0; ks < 4; ks++) {
            #pragma unroll
            for (int jt = 0; jt < 8; jt++) {
                // b-frag: B[k=d][n=kv]; lane: kv = 8jt + g, d = 16ks + 2qq (+1), +8
                const float* kp = Ks + (jt * 8 + g) * KSTR + ks * 16 + 2 * qq;
                float2 kA = *(const float2*)(kp);
                float2 kB = *(const float2*)(kp + 8);
                uint32_t bhh[2], bll[2];
                split2(kA.x, kA.y, bhh[0], bll[0]);
                split2(kB.x, kB.y, bhh[1], bll[1]);
                mma_bf16(S[jt], qh[ks], bhh);
                mma_bf16(S[jt], qh[ks], bll);
                mma_bf16(S[jt], ql[ks], bhh);
            }
        }

        // ---- online softmax (rows r -> c0,c1 ; r+8 -> c2,c3) ----
        float mx0 = -1e30f, mx1 = -1e30f;
        #pragma unroll
        for (int j = 0; j < 8; j++) {
            mx0 = fmaxf(mx0, fmaxf(S[j][0], S[j][1]));
            mx1 = fmaxf(mx1, fmaxf(S[j][2], S[j][3]));
        }
        mx0 = fmaxf(mx0, __shfl_xor_sync(0xffffffffu, mx0, 1));
        mx0 = fmaxf(mx0, __shfl_xor_sync(0xffffffffu, mx0, 2));
        mx1 = fmaxf(mx1, __shfl_xor_sync(0xffffffffu, mx1, 1));
        mx1 = fmaxf(mx1, __shfl_xor_sync(0xffffffffu, mx1, 2));

        const float mn0 = fmaxf(m0, mx0);
        const float mn1 = fmaxf(m1, mx1);
        const float c0 = __expf(m0 - mn0);
        const float c1 = __expf(m1 - mn1);
        m0 = mn0; m1 = mn1;
        l0 *= c0; l1 *= c1;
        #pragma unroll
        for (int j = 0; j < 8; j++) {
            O[j][0] *= c0; O[j][1] *= c0;
            O[j][2] *= c1; O[j][3] *= c1;
        }

        // exp -> probabilities (kept in S), accumulate lane-partial sums
        #pragma unroll
        for (int j = 0; j < 8; j++) {
            S[j][0] = __expf(S[j][0] - mn0);
            S[j][1] = __expf(S[j][1] - mn0);
            S[j][2] = __expf(S[j][2] - mn1);
            S[j][3] = __expf(S[j][3] - mn1);
            l0 += S[j][0] + S[j][1];
            l1 += S[j][2] + S[j][3];
        }

        // ---- PV: O += P[16q x 64kv] @ V[64kv x 64d], 3-term bf16 ----
        #pragma unroll
        for (int kvs = 0; kvs < 4; kvs++) {
            // a-frags straight from S accumulator layout (tiles 2kvs, 2kvs+1)
            uint32_t ah[4], al[4];
            split2(S[2 * kvs][0],     S[2 * kvs][1],     ah[0], al[0]);
            split2(S[2 * kvs][2],     S[2 * kvs][3],     ah[1], al[1]);
            split2(S[2 * kvs + 1][0], S[2 * kvs + 1][1], ah[2], al[2]);
            split2(S[2 * kvs + 1][2], S[2 * kvs + 1][3], ah[3], al[3]);
            #pragma unroll
            for (int dt = 0; dt < 8; dt++) {
                // b-frag: B[k=kv][n=d]; lane: kv = 16kvs + 2qq (+1), +8; d = 8dt + g
                const float* vp = Vs + (kvs * 16 + 2 * qq) * VSTR + dt * 8 + g;
                float v00 = vp[0];
                float v01 = vp[VSTR];
                float v10 = vp[8 * VSTR];
                float v11 = vp[9 * VSTR];
                uint32_t bvh[2], bvl[2];
                split2(v00, v01, bvh[0], bvl[0]);
                split2(v10, v11, bvh[1], bvl[1]);
                mma_bf16(O[dt], ah, bvh);
                mma_bf16(O[dt], ah, bvl);
                mma_bf16(O[dt], al, bvh);
            }
        }
    }

    // ---- finalize ----
    l0 += __shfl_xor_sync(0xffffffffu, l0, 1);
    l0 += __shfl_xor_sync(0xffffffffu, l0, 2);
    l1 += __shfl_xor_sync(0xffffffffu, l1, 1);
    l1 += __shfl_xor_sync(0xffffffffu, l1, 2);
    const float i0 = 1.f / l0;
    const float i1 = 1.f / l1;

    float* c0p = C + (size_t)(b * L_ + r) * D_ + h * DH_;
    float* c1p = C + (size_t)(b * L_ + r + 8) * D_ + h * DH_;
    #pragma unroll
    for (int dt = 0; dt < 8; dt++) {
        const int d0 = dt * 8 + 2 * qq;
        *(float2*)(c0p + d0) = make_float2(O[dt][0] * i0, O[dt][1] * i0);
        *(float2*)(c1p + d0) = make_float2(O[dt][2] * i1, O[dt][3] * i1);
    }
}

// ---------------------------------------------------------------------------
extern "C" void kernel_launch(void* const* d_in, const int* in_sizes, int n_in,
                              void* d_out, int out_size)
{
    const float* hs  = (const float*)d_in[0];
    const float* Wq  = (const float*)d_in[1];
    const float* Wk  = (const float*)d_in[2];
    const float* Wv  = (const float*)d_in[3];
    const float* Wo  = (const float*)d_in[4];
    const float* bo  = (const float*)d_in[5];
    const float* Kbg = (const float*)d_in[6];
    const float* Vbg = (const float*)d_in[7];
    float* out = (float*)d_out;

    float *q, *k, *v, *c;
    cudaGetSymbolAddress((void**)&q, g_Q);
    cudaGetSymbolAddress((void**)&k, g_K);
    cudaGetSymbolAddress((void**)&v, g_V);
    cudaGetSymbolAddress((void**)&c, g_C);

    dim3 gg(N_ / 128, M_ / 128);   // (10, 32)
    tf32_gemm_kernel<<<gg, 256>>>(hs, Wq, nullptr, q);
    tf32_gemm_kernel<<<gg, 256>>>(hs, Wk, nullptr, k);
    tf32_gemm_kernel<<<gg, 256>>>(hs, Wv, nullptr, v);

    attn_mma_kernel<<<dim3(L_ / 64, BH_), 128>>>(q, k, v, Kbg, Vbg, c);

    tf32_gemm_kernel<<<gg, 256>>>(c, Wo, bo, out);
}

// round 17
// speedup vs baseline: 2.7841x; 1.0434x over previous
#include <cuda_runtime.h>
#include <cuda_bf16.h>
#include <cstdint>

#define B_   4
#define L_   1024
#define D_   1280
#define H_   20
#define DH_  64
#define BH_  80            // B_*H_
#define M_   4096          // B_*L_
#define K_   1280
#define N_   1280
#define KV_  2048          // L_ + L_ background
#define ALPHA 0.48f
#define QSCALE 0.125f      // 1/sqrt(64)

// Scratch (device globals: allocation-free per harness rules)
__device__ float g_Q[M_ * D_];
__device__ float g_K[M_ * D_];
__device__ float g_V[M_ * D_];
__device__ float g_C[M_ * D_];
// pre-split bf16x2 K (d-pair packed) and V (kv-pair packed, transposed)
__device__ uint32_t g_Kc_hi[BH_ * KV_ * 32];
__device__ uint32_t g_Kc_lo[BH_ * KV_ * 32];
__device__ uint32_t g_Vt_hi[BH_ * DH_ * (KV_ / 2)];
__device__ uint32_t g_Vt_lo[BH_ * DH_ * (KV_ / 2)];

// ---------------------------------------------------------------------------
// TF32 tensor-core GEMM: C[M,1280] = A[M,1280] @ B[1280,1280] (+bias)
// ---------------------------------------------------------------------------
__device__ __forceinline__ uint32_t f2tf(float f) {
    uint32_t u;
    asm("cvt.rna.tf32.f32 %0, %1;" : "=r"(u) : "f"(f));
    return u;
}

__device__ __forceinline__ void mma_tf32(float* c, const uint32_t* a, const uint32_t* b) {
    asm volatile(
        "mma.sync.aligned.m16n8k8.row.col.f32.tf32.tf32.f32 "
        "{%0,%1,%2,%3}, {%4,%5,%6,%7}, {%8,%9}, {%0,%1,%2,%3};\n"
        : "+f"(c[0]), "+f"(c[1]), "+f"(c[2]), "+f"(c[3])
        : "r"(a[0]), "r"(a[1]), "r"(a[2]), "r"(a[3]), "r"(b[0]), "r"(b[1]));
}

#define AS_STRIDE 20
#define BS_STRIDE 136

__global__ __launch_bounds__(256) void tf32_gemm_kernel(
    const float* __restrict__ A, const float* __restrict__ Bm,
    const float* __restrict__ bias, float* __restrict__ C)
{
    __shared__ uint32_t As[128 * AS_STRIDE];
    __shared__ uint32_t Bs[16 * BS_STRIDE];

    const int tid  = threadIdx.x;
    const int brow = blockIdx.y * 128;
    const int bcol = blockIdx.x * 128;

    const int lane   = tid & 31;
    const int warp   = tid >> 5;
    const int warp_m = (warp >> 1) * 32;
    const int warp_n = (warp & 1) * 64;
    const int g      = lane >> 2;
    const int q      = lane & 3;

    const int arow = tid >> 1;
    const int ac8  = (tid & 1) * 8;
    const int bkr  = tid >> 4;
    const int bc8  = (tid & 15) * 8;

    const float* Ap = A + (size_t)(brow + arow) * K_ + ac8;
    const float* Bp = Bm + (size_t)bkr * N_ + bcol + bc8;

    float acc[2][8][4];
    #pragma unroll
    for (int i = 0; i < 2; i++)
        #pragma unroll
        for (int j = 0; j < 8; j++)
            #pragma unroll
            for (int r = 0; r < 4; r++) acc[i][j][r] = 0.f;

    for (int k0 = 0; k0 < K_; k0 += 16) {
        float4 a4a = *(const float4*)(Ap + k0);
        float4 a4b = *(const float4*)(Ap + k0 + 4);
        float4 b4a = *(const float4*)(Bp + (size_t)k0 * N_);
        float4 b4b = *(const float4*)(Bp + (size_t)k0 * N_ + 4);

        uint32_t* asd = &As[arow * AS_STRIDE + ac8];
        asd[0] = f2tf(a4a.x); asd[1] = f2tf(a4a.y);
        asd[2] = f2tf(a4a.z); asd[3] = f2tf(a4a.w);
        asd[4] = f2tf(a4b.x); asd[5] = f2tf(a4b.y);
        asd[6] = f2tf(a4b.z); asd[7] = f2tf(a4b.w);

        uint32_t* bsd = &Bs[bkr * BS_STRIDE + bc8];
        bsd[0] = f2tf(b4a.x); bsd[1] = f2tf(b4a.y);
        bsd[2] = f2tf(b4a.z); bsd[3] = f2tf(b4a.w);
        bsd[4] = f2tf(b4b.x); bsd[5] = f2tf(b4b.y);
        bsd[6] = f2tf(b4b.z); bsd[7] = f2tf(b4b.w);

        __syncthreads();

        #pragma unroll
        for (int ks = 0; ks < 16; ks += 8) {
            uint32_t af[2][4];
            #pragma unroll
            for (int i = 0; i < 2; i++) {
                const int m0 = warp_m + i * 16 + g;
                af[i][0] = As[m0 * AS_STRIDE + ks + q];
                af[i][1] = As[(m0 + 8) * AS_STRIDE + ks + q];
                af[i][2] = As[m0 * AS_STRIDE + ks + q + 4];
                af[i][3] = As[(m0 + 8) * AS_STRIDE + ks + q + 4];
            }
            #pragma unroll
            for (int j = 0; j < 8; j++) {
                uint32_t bf[2];
                const int n0 = warp_n + j * 8 + g;
                bf[0] = Bs[(ks + q) * BS_STRIDE + n0];
                bf[1] = Bs[(ks + q + 4) * BS_STRIDE + n0];
                mma_tf32(acc[0][j], af[0], bf);
                mma_tf32(acc[1][j], af[1], bf);
            }
        }
        __syncthreads();
    }

    #pragma unroll
    for (int i = 0; i < 2; i++) {
        const int row0 = brow + warp_m + i * 16 + g;
        #pragma unroll
        for (int j = 0; j < 8; j++) {
            const int col = bcol + warp_n + j * 8 + 2 * q;
            float b0 = 0.f, b1 = 0.f;
            if (bias) { b0 = bias[col]; b1 = bias[col + 1]; }
            float2 v0 = make_float2(acc[i][j][0] + b0, acc[i][j][1] + b1);
            float2 v1 = make_float2(acc[i][j][2] + b0, acc[i][j][3] + b1);
            *(float2*)(C + (size_t)row0 * N_ + col) = v0;
            *(float2*)(C + (size_t)(row0 + 8) * N_ + col) = v1;
        }
    }
}

// ---------------------------------------------------------------------------
// hi/lo bf16 split helpers
// ---------------------------------------------------------------------------
__device__ __forceinline__ void split2(float x, float y, uint32_t& hi, uint32_t& lo) {
    __nv_bfloat162 h2 = __floats2bfloat162_rn(x, y);
    float rx = x - __bfloat162float(h2.x);
    float ry = y - __bfloat162float(h2.y);
    __nv_bfloat162 l2 = __floats2bfloat162_rn(rx, ry);
    hi = *reinterpret_cast<uint32_t*>(&h2);
    lo = *reinterpret_cast<uint32_t*>(&l2);
}

__device__ __forceinline__ void mma_bf16(float* c, const uint32_t* a, const uint32_t* b) {
    asm volatile(
        "mma.sync.aligned.m16n8k16.row.col.f32.bf16.bf16.f32 "
        "{%0,%1,%2,%3}, {%4,%5,%6,%7}, {%8,%9}, {%0,%1,%2,%3};\n"
        : "+f"(c[0]), "+f"(c[1]), "+f"(c[2]), "+f"(c[3])
        : "r"(a[0]), "r"(a[1]), "r"(a[2]), "r"(a[3]), "r"(b[0]), "r"(b[1]));
}

// ---------------------------------------------------------------------------
// prep_k: build Kc_hi/lo[bh][kv=0..2047][32 d-pairs]; bg half scaled by alpha
// ---------------------------------------------------------------------------
__global__ __launch_bounds__(256) void prep_k_kernel(
    const float* __restrict__ K, const float* __restrict__ Kbg)
{
    const int idx = blockIdx.x * 256 + threadIdx.x;   // < BH_*2048*32
    const int p   = idx & 31;
    const int kv  = (idx >> 5) & (KV_ - 1);
    const int bh  = idx >> 16;                        // 2048*32 = 1<<16
    const int b   = bh / H_;
    const int h   = bh % H_;
    float2 x;
    if (kv < L_) {
        x = *(const float2*)(K + (size_t)(b * L_ + kv) * D_ + h * DH_ + 2 * p);
    } else {
        x = *(const float2*)(Kbg + ((size_t)bh * L_ + kv - L_) * DH_ + 2 * p);
        x.x *= ALPHA; x.y *= ALPHA;
    }
    uint32_t hi, lo;
    split2(x.x, x.y, hi, lo);
    g_Kc_hi[idx] = hi;
    g_Kc_lo[idx] = lo;
}

// ---------------------------------------------------------------------------
// prep_v: build transposed Vt_hi/lo[bh][d=0..63][1024 kv-pairs] via smem tile
// block = (kv-tile of 64, bh); whole tile is either self or bg
// ---------------------------------------------------------------------------
#define TSTR 65
__global__ __launch_bounds__(256) void prep_v_kernel(
    const float* __restrict__ V, const float* __restrict__ Vbg)
{
    __shared__ float T[64 * TSTR];
    const int bh  = blockIdx.y;
    const int kv0 = blockIdx.x * 64;
    const int b   = bh / H_;
    const int h   = bh % H_;
    const int tid = threadIdx.x;

    #pragma unroll
    for (int i = 0; i < 4; i++) {
        const int slot = tid + i * 256;     // 1024 float4 slots
        const int row  = slot >> 4;
        const int c4   = (slot & 15) << 2;
        float4 v;
        if (kv0 < L_) {
            v = *(const float4*)(V + (size_t)(b * L_ + kv0 + row) * D_ + h * DH_ + c4);
        } else {
            v = *(const float4*)(Vbg + ((size_t)bh * L_ + kv0 - L_ + row) * DH_ + c4);
            v.x *= ALPHA; v.y *= ALPHA; v.z *= ALPHA; v.w *= ALPHA;
        }
        float* tp = &T[row * TSTR + c4];
        tp[0] = v.x; tp[1] = v.y; tp[2] = v.z; tp[3] = v.w;
    }
    __syncthreads();

    #pragma unroll
    for (int i = 0; i < 8; i++) {
        const int slot = tid + i * 256;     // 2048 outputs
        const int d    = slot >> 5;
        const int kp   = slot & 31;
        uint32_t hi, lo;
        split2(T[(2 * kp) * TSTR + d], T[(2 * kp + 1) * TSTR + d], hi, lo);
        const size_t o = ((size_t)bh * DH_ + d) * (KV_ / 2) + (kv0 >> 1) + kp;
        g_Vt_hi[o] = hi;
        g_Vt_lo[o] = lo;
    }
}

// ---------------------------------------------------------------------------
// bf16-split tensor flash attention, pre-split K/V (no in-loop cvt on K/V).
// Block: 64 q-rows, 4 warps x 16 rows. KV tiles of 64 (32 iters).
// smem stride 36: frag-load bank = (4g+qq)%32 — perfect permutation.
// ---------------------------------------------------------------------------
#define CSTR 36

__global__ __launch_bounds__(128) void attn_mma_kernel(
    const float* __restrict__ Q, float* __restrict__ C)
{
    __shared__ uint32_t KhiS[64 * CSTR], KloS[64 * CSTR];
    __shared__ uint32_t VhiS[64 * CSTR], VloS[64 * CSTR];

    const int bh    = blockIdx.y;
    const int b     = bh / H_;
    const int h     = bh % H_;
    const int qbase = blockIdx.x * 64;
    const int tid   = threadIdx.x;
    const int lane  = tid & 31;
    const int warp  = tid >> 5;
    const int g     = lane >> 2;     // 0..7
    const int qq    = lane & 3;      // 0..3

    const int r = qbase + warp * 16 + g;    // lane's q rows: r, r+8

    // ---- load + pre-split Q fragments (held for whole kernel) ----
    uint32_t qh[4][4], ql[4][4];
    {
        const float* q0 = Q + (size_t)(b * L_ + r) * D_ + h * DH_;
        const float* q1 = Q + (size_t)(b * L_ + r + 8) * D_ + h * DH_;
        #pragma unroll
        for (int kf = 0; kf < 4; kf++) {
            const int d0 = kf * 16 + 2 * qq;
            split2(q0[d0] * QSCALE,     q0[d0 + 1] * QSCALE, qh[kf][0], ql[kf][0]);
            split2(q1[d0] * QSCALE,     q1[d0 + 1] * QSCALE, qh[kf][1], ql[kf][1]);
            split2(q0[d0 + 8] * QSCALE, q0[d0 + 9] * QSCALE, qh[kf][2], ql[kf][2]);
            split2(q1[d0 + 8] * QSCALE, q1[d0 + 9] * QSCALE, qh[kf][3], ql[kf][3]);
        }
    }

    float O[8][4];
    #pragma unroll
    for (int j = 0; j < 8; j++)
        #pragma unroll
        for (int i = 0; i < 4; i++) O[j][i] = 0.f;
    float m0 = -1e30f, m1 = -1e30f;
    float l0 = 0.f,    l1 = 0.f;

    const uint32_t* kc_hi = g_Kc_hi + (size_t)bh * KV_ * 32;
    const uint32_t* kc_lo = g_Kc_lo + (size_t)bh * KV_ * 32;
    const uint32_t* vt_hi = g_Vt_hi + (size_t)bh * DH_ * (KV_ / 2);
    const uint32_t* vt_lo = g_Vt_lo + (size_t)bh * DH_ * (KV_ / 2);

    for (int t = 0; t < 32; t++) {
        __syncthreads();
        // ---- fill tile: K rows kv-major [64][32], V rows d-major [64][32] ----
        #pragma unroll
        for (int i = 0; i < 4; i++) {
            const int slot = tid + i * 128;   // 512 uint4 slots per array
            const int row  = slot >> 3;
            const int p4   = (slot & 7) * 4;
            *(uint4*)&KhiS[row * CSTR + p4] = *(const uint4*)(kc_hi + ((size_t)(t * 64 + row)) * 32 + p4);
            *(uint4*)&KloS[row * CSTR + p4] = *(const uint4*)(kc_lo + ((size_t)(t * 64 + row)) * 32 + p4);
            *(uint4*)&VhiS[row * CSTR + p4] = *(const uint4*)(vt_hi + (size_t)row * (KV_ / 2) + t * 32 + p4);
            *(uint4*)&VloS[row * CSTR + p4] = *(const uint4*)(vt_lo + (size_t)row * (KV_ / 2) + t * 32 + p4);
        }
        __syncthreads();

        // ---- scores S[16q x 64kv]: 3-term bf16 mma, b-frags direct LDS ----
        float S[8][4];
        #pragma unroll
        for (int j = 0; j < 8; j++)
            #pragma unroll
            for (int i = 0; i < 4; i++) S[j][i] = 0.f;

        #pragma unroll
        for (int ks = 0; ks < 4; ks++) {
            #pragma unroll
            for (int jt = 0; jt < 8; jt++) {
                const uint32_t* kb = &KhiS[(jt * 8 + g) * CSTR + ks * 8 + qq];
                const uint32_t* kl = &KloS[(jt * 8 + g) * CSTR + ks * 8 + qq];
                uint32_t bh2[2] = { kb[0], kb[4] };
                uint32_t bl2[2] = { kl[0], kl[4] };
                mma_bf16(S[jt], qh[ks], bh2);
                mma_bf16(S[jt], qh[ks], bl2);
                mma_bf16(S[jt], ql[ks], bh2);
            }
        }

        // ---- online softmax ----
        float mx0 = -1e30f, mx1 = -1e30f;
        #pragma unroll
        for (int j = 0; j < 8; j++) {
            mx0 = fmaxf(mx0, fmaxf(S[j][0], S[j][1]));
            mx1 = fmaxf(mx1, fmaxf(S[j][2], S[j][3]));
        }
        mx0 = fmaxf(mx0, __shfl_xor_sync(0xffffffffu, mx0, 1));
        mx0 = fmaxf(mx0, __shfl_xor_sync(0xffffffffu, mx0, 2));
        mx1 = fmaxf(mx1, __shfl_xor_sync(0xffffffffu, mx1, 1));
        mx1 = fmaxf(mx1, __shfl_xor_sync(0xffffffffu, mx1, 2));

        const float mn0 = fmaxf(m0, mx0);
        const float mn1 = fmaxf(m1, mx1);
        const float c0 = __expf(m0 - mn0);
        const float c1 = __expf(m1 - mn1);
        m0 = mn0; m1 = mn1;
        l0 *= c0; l1 *= c1;
        #pragma unroll
        for (int j = 0; j < 8; j++) {
            O[j][0] *= c0; O[j][1] *= c0;
            O[j][2] *= c1; O[j][3] *= c1;
        }

        #pragma unroll
        for (int j = 0; j < 8; j++) {
            S[j][0] = __expf(S[j][0] - mn0);
            S[j][1] = __expf(S[j][1] - mn0);
            S[j][2] = __expf(S[j][2] - mn1);
            S[j][3] = __expf(S[j][3] - mn1);
            l0 += S[j][0] + S[j][1];
            l1 += S[j][2] + S[j][3];
        }

        // ---- PV: O += P @ V, 3-term; V b-frags direct LDS ----
        #pragma unroll
        for (int kvs = 0; kvs < 4; kvs++) {
            uint32_t ah[4], al[4];
            split2(S[2 * kvs][0],     S[2 * kvs][1],     ah[0], al[0]);
            split2(S[2 * kvs][2],     S[2 * kvs][3],     ah[1], al[1]);
            split2(S[2 * kvs + 1][0], S[2 * kvs + 1][1], ah[2], al[2]);
            split2(S[2 * kvs + 1][2], S[2 * kvs + 1][3], ah[3], al[3]);
            #pragma unroll
            for (int dt = 0; dt < 8; dt++) {
                const uint32_t* vb = &VhiS[(dt * 8 + g) * CSTR + kvs * 8 + qq];
                const uint32_t* vl = &VloS[(dt * 8 + g) * CSTR + kvs * 8 + qq];
                uint32_t bvh2[2] = { vb[0], vb[4] };
                uint32_t bvl2[2] = { vl[0], vl[4] };
                mma_bf16(O[dt], ah, bvh2);
                mma_bf16(O[dt], ah, bvl2);
                mma_bf16(O[dt], al, bvh2);
            }
        }
    }

    // ---- finalize ----
    l0 += __shfl_xor_sync(0xffffffffu, l0, 1);
    l0 += __shfl_xor_sync(0xffffffffu, l0, 2);
    l1 += __shfl_xor_sync(0xffffffffu, l1, 1);
    l1 += __shfl_xor_sync(0xffffffffu, l1, 2);
    const float i0 = 1.f / l0;
    const float i1 = 1.f / l1;

    float* c0p = C + (size_t)(b * L_ + r) * D_ + h * DH_;
    float* c1p = C + (size_t)(b * L_ + r + 8) * D_ + h * DH_;
    #pragma unroll
    for (int dt = 0; dt < 8; dt++) {
        const int d0 = dt * 8 + 2 * qq;
        *(float2*)(c0p + d0) = make_float2(O[dt][0] * i0, O[dt][1] * i0);
        *(float2*)(c1p + d0) = make_float2(O[dt][2] * i1, O[dt][3] * i1);
    }
}

// ---------------------------------------------------------------------------
extern "C" void kernel_launch(void* const* d_in, const int* in_sizes, int n_in,
                              void* d_out, int out_size)
{
    const float* hs  = (const float*)d_in[0];
    const float* Wq  = (const float*)d_in[1];
    const float* Wk  = (const float*)d_in[2];
    const float* Wv  = (const float*)d_in[3];
    const float* Wo  = (const float*)d_in[4];
    const float* bo  = (const float*)d_in[5];
    const float* Kbg = (const float*)d_in[6];
    const float* Vbg = (const float*)d_in[7];
    float* out = (float*)d_out;

    float *q, *k, *v, *c;
    cudaGetSymbolAddress((void**)&q, g_Q);
    cudaGetSymbolAddress((void**)&k, g_K);
    cudaGetSymbolAddress((void**)&v, g_V);
    cudaGetSymbolAddress((void**)&c, g_C);

    dim3 gg(N_ / 128, M_ / 128);   // (10, 32)
    tf32_gemm_kernel<<<gg, 256>>>(hs, Wq, nullptr, q);
    tf32_gemm_kernel<<<gg, 256>>>(hs, Wk, nullptr, k);
    tf32_gemm_kernel<<<gg, 256>>>(hs, Wv, nullptr, v);

    prep_k_kernel<<<(BH_ * KV_ * 32) / 256, 256>>>(k, Kbg);
    prep_v_kernel<<<dim3(KV_ / 64, BH_), 256>>>(v, Vbg);

    attn_mma_kernel<<<dim3(L_ / 64, BH_), 128>>>(q, out != nullptr ? c : c);

    tf32_gemm_kernel<<<gg, 256>>>(c, Wo, bo, out);
}